// round 5
// baseline (speedup 1.0000x reference)
#include <cuda_runtime.h>
#include <cstdint>
#include <cstddef>

#define Bsz 128
#define Tt  2048
#define Cin 16
#define CO  128
#define Hh  128
#define Gg  512

// -------- scratch (no allocations allowed; __device__ globals are the sanctioned path) ------
__device__ float g_seq[(size_t)Bsz * Tt * CO];      // conv output, [b*T+t][co]
__device__ float g_x0 [(size_t)Bsz * Tt * Gg];      // layer-0 input projection, [b*T+t][g]
__device__ float g_pooled[Bsz * Hh];                // mean over t of h1

// ============================ kernel 1: conv1d(k=3,pad=1) + LeakyReLU ============================
__global__ void conv_kernel(const float* __restrict__ x, const float* __restrict__ cw,
                            const float* __restrict__ cb) {
    __shared__ float xs[130 * 16];     // t0-1 .. t0+128
    __shared__ float wct[48 * 128];    // [(c*3+kk)][co]
    __shared__ float cbs[128];
    int tid = threadIdx.x;
    int b = blockIdx.y, t0 = blockIdx.x * 128;
    for (int i = tid; i < 130 * 16; i += 256) {
        int row = i >> 4, c = i & 15;
        int t = t0 - 1 + row;
        xs[i] = (t >= 0 && t < Tt) ? x[((size_t)b * Tt + t) * Cin + c] : 0.0f;
    }
    for (int i = tid; i < 48 * 128; i += 256) {
        int co = i / 48, rem = i % 48;          // rem = c*3 + kk
        wct[rem * 128 + co] = cw[i];
    }
    if (tid < 128) cbs[tid] = cb[tid];
    __syncthreads();
    for (int idx = tid; idx < 128 * 128; idx += 256) {
        int tl = idx >> 7, co = idx & 127;
        float acc = cbs[co];
#pragma unroll
        for (int c = 0; c < 16; c++)
#pragma unroll
            for (int kk = 0; kk < 3; kk++)
                acc += xs[(tl + kk) * 16 + c] * wct[(c * 3 + kk) * 128 + co];
        acc = acc >= 0.f ? acc : 0.01f * acc;
        g_seq[((size_t)b * Tt + t0 + tl) * CO + co] = acc;
    }
}

// ============================ kernel 2: x0 = seq @ w_ih0^T + (b_ih0+b_hh0) ============================
// block tile: 128 (M) x 64 (N), K = 128 fully in smem. 256 threads, 8x4 register tiles.
#define PROJ_SMEM_BYTES ((128 * 132 + 128 * 64) * 4)
__global__ void proj_kernel(const float* __restrict__ w, const float* __restrict__ bi,
                            const float* __restrict__ bh) {
    extern __shared__ float sm[];
    float* As = sm;                 // [128][132] (padded)
    float* Ws = sm + 128 * 132;     // [k=128][n=64]
    int tid = threadIdx.x;
    int mt = blockIdx.x, nt = blockIdx.y;
    const float* Ab = g_seq + (size_t)mt * 128 * CO;
    for (int i = tid; i < 128 * 32; i += 256) {
        int row = i >> 5, c4 = i & 31;
        float4 v = reinterpret_cast<const float4*>(Ab)[(size_t)row * 32 + c4];
        float* d = As + row * 132 + c4 * 4;
        d[0] = v.x; d[1] = v.y; d[2] = v.z; d[3] = v.w;
    }
    for (int i = tid; i < 64 * 128; i += 256) {
        int n = i >> 7, k = i & 127;
        Ws[k * 64 + n] = w[(size_t)(nt * 64 + n) * CO + k];
    }
    __syncthreads();
    int ty = tid >> 4, tx = tid & 15;
    float acc[8][4];
#pragma unroll
    for (int i = 0; i < 8; i++) { acc[i][0] = acc[i][1] = acc[i][2] = acc[i][3] = 0.f; }
#pragma unroll 4
    for (int k = 0; k < 128; k++) {
        float4 wv = *reinterpret_cast<const float4*>(Ws + k * 64 + tx * 4);
#pragma unroll
        for (int i = 0; i < 8; i++) {
            float a = As[(ty * 8 + i) * 132 + k];
            acc[i][0] += a * wv.x; acc[i][1] += a * wv.y;
            acc[i][2] += a * wv.z; acc[i][3] += a * wv.w;
        }
    }
    int n0 = nt * 64 + tx * 4;
    float bb0 = bi[n0] + bh[n0], bb1 = bi[n0 + 1] + bh[n0 + 1];
    float bb2 = bi[n0 + 2] + bh[n0 + 2], bb3 = bi[n0 + 3] + bh[n0 + 3];
#pragma unroll
    for (int i = 0; i < 8; i++) {
        float4 o;
        o.x = acc[i][0] + bb0; o.y = acc[i][1] + bb1;
        o.z = acc[i][2] + bb2; o.w = acc[i][3] + bb3;
        *reinterpret_cast<float4*>(g_x0 + ((size_t)mt * 128 + ty * 8 + i) * Gg + n0) = o;
    }
}

// ============================ kernel 3: persistent 2-layer LSTM, cluster-of-4 ============================
// 32 clusters x 4 CTAs. Cluster owns 4 batch rows. CTA r owns gate rows {q*128 + r*32 + j}.
// Weights (3 x 128 x 128 fp32, padded rows of 132) resident in smem per CTA.
// h0/h1 double-buffered and broadcast to all 4 CTAs via DSMEM; 2 cluster barriers/step.

__device__ __forceinline__ float sigf(float x)  { return 1.0f / (1.0f + __expf(-x)); }
__device__ __forceinline__ float tanhf_(float x) { return 2.0f / (1.0f + __expf(-2.0f * x)) - 1.0f; }

__device__ __forceinline__ void st_dsmem(uint32_t la, int rk, float v) {
    uint32_t ra;
    asm volatile("mapa.shared::cluster.u32 %0, %1, %2;" : "=r"(ra) : "r"(la), "r"(rk));
    asm volatile("st.shared::cluster.f32 [%0], %1;" :: "r"(ra), "f"(v) : "memory");
}
#define CLUSTER_SYNC() do { \
    asm volatile("barrier.cluster.arrive.aligned;" ::: "memory"); \
    asm volatile("barrier.cluster.wait.aligned;"   ::: "memory"); } while (0)

#define LSTM_SMEM_BYTES ((3 * 128 * 132 + 1024 + 1024 + 512) * 4)

__global__ void __cluster_dims__(4, 1, 1) __launch_bounds__(128, 1)
lstm_kernel(const float* __restrict__ whh0, const float* __restrict__ wih1,
            const float* __restrict__ whh1, const float* __restrict__ bih1,
            const float* __restrict__ bhh1) {
    extern __shared__ float sm[];
    float* w0   = sm;                       // W_hh0 slice [128][132]
    float* w1   = w0 + 128 * 132;           // W_ih1 slice
    float* w2   = w1 + 128 * 132;           // W_hh1 slice
    float* h0f  = w2 + 128 * 132;           // [2 buf][4 b][128 k]
    float* h1f  = h0f + 1024;               // [2][4][128]
    float* gtmp = h1f + 1024;               // [4 q][32 j][4 b]

    int tid = threadIdx.x;
    int q = tid >> 5, j = tid & 31;
    uint32_t rank; asm("mov.u32 %0, %%cluster_ctarank;" : "=r"(rank));
    int r  = (int)rank;
    int b0 = (blockIdx.x >> 2) * 4;

    // load weight slices (rows: q'*128 + r*32 + j' -> local row q'*32 + j')
    for (int i = tid; i < 128 * 128; i += 128) {
        int rl = i >> 7, k = i & 127;
        int rg = ((rl >> 5) << 7) + (r << 5) + (rl & 31);
        w0[rl * 132 + k] = whh0[(size_t)rg * Hh + k];
        w1[rl * 132 + k] = wih1[(size_t)rg * Hh + k];
        w2[rl * 132 + k] = whh1[(size_t)rg * Hh + k];
    }
    for (int i = tid; i < 1024; i += 128) { h0f[i] = 0.f; h1f[i] = 0.f; }

    int rowg = (q << 7) + (r << 5) + j;       // global gate row owned in GEMM role
    float b1v = bih1[rowg] + bhh1[rowg];
    int hlocal = (r << 5) + j;                 // h index owned in elementwise role (batch = q)
    float c0 = 0.f, c1 = 0.f, pool = 0.f;

    float xn[4];
#pragma unroll
    for (int bb = 0; bb < 4; bb++)
        xn[bb] = g_x0[((size_t)(b0 + bb) * Tt) * Gg + rowg];

    uint32_t la0base = (uint32_t)__cvta_generic_to_shared(h0f);
    uint32_t la1base = (uint32_t)__cvta_generic_to_shared(h1f);

    __syncthreads();
    CLUSTER_SYNC();   // init complete everywhere before any DSMEM traffic

    const float4* wr0 = reinterpret_cast<const float4*>(w0 + (q * 32 + j) * 132);
    const float4* wr1 = reinterpret_cast<const float4*>(w1 + (q * 32 + j) * 132);
    const float4* wr2 = reinterpret_cast<const float4*>(w2 + (q * 32 + j) * 132);

    int p = 0;
    for (int t = 0; t < Tt; t++) {
        float acc[4];
#pragma unroll
        for (int bb = 0; bb < 4; bb++) acc[bb] = xn[bb];
        if (t + 1 < Tt) {
#pragma unroll
            for (int bb = 0; bb < 4; bb++)
                xn[bb] = g_x0[((size_t)(b0 + bb) * Tt + (t + 1)) * Gg + rowg];
        }
        // ---- layer 0 gates: acc[b] += W_hh0[row,:] . h0[b,:]
        {
            const float4* hb = reinterpret_cast<const float4*>(h0f + p * 512);
#pragma unroll
            for (int k4 = 0; k4 < 32; k4++) {
                float4 w = wr0[k4];
#pragma unroll
                for (int bb = 0; bb < 4; bb++) {
                    float4 h = hb[bb * 32 + k4];
                    acc[bb] += w.x * h.x; acc[bb] += w.y * h.y;
                    acc[bb] += w.z * h.z; acc[bb] += w.w * h.w;
                }
            }
        }
#pragma unroll
        for (int bb = 0; bb < 4; bb++) gtmp[(q << 7) + (j << 2) + bb] = acc[bb];
        __syncthreads();
        {   // elementwise: this thread owns (batch=q, h=hlocal)
            float gi = gtmp[  0 + (j << 2) + q];
            float gf = gtmp[128 + (j << 2) + q];
            float gg = gtmp[256 + (j << 2) + q];
            float go = gtmp[384 + (j << 2) + q];
            float cn = sigf(gf) * c0 + sigf(gi) * tanhf_(gg);
            float hn = sigf(go) * tanhf_(cn);
            c0 = cn;
            uint32_t la = la0base + (uint32_t)(((1 - p) * 512 + (q << 7) + hlocal) * 4);
            st_dsmem(la, 0, hn); st_dsmem(la, 1, hn); st_dsmem(la, 2, hn); st_dsmem(la, 3, hn);
        }
        CLUSTER_SYNC();

        // ---- layer 1 gates: b1 + W_ih1 . h0_new + W_hh1 . h1_old
#pragma unroll
        for (int bb = 0; bb < 4; bb++) acc[bb] = b1v;
        {
            const float4* hbn = reinterpret_cast<const float4*>(h0f + (1 - p) * 512);
#pragma unroll
            for (int k4 = 0; k4 < 32; k4++) {
                float4 w = wr1[k4];
#pragma unroll
                for (int bb = 0; bb < 4; bb++) {
                    float4 h = hbn[bb * 32 + k4];
                    acc[bb] += w.x * h.x; acc[bb] += w.y * h.y;
                    acc[bb] += w.z * h.z; acc[bb] += w.w * h.w;
                }
            }
            const float4* hb1 = reinterpret_cast<const float4*>(h1f + p * 512);
#pragma unroll
            for (int k4 = 0; k4 < 32; k4++) {
                float4 w = wr2[k4];
#pragma unroll
                for (int bb = 0; bb < 4; bb++) {
                    float4 h = hb1[bb * 32 + k4];
                    acc[bb] += w.x * h.x; acc[bb] += w.y * h.y;
                    acc[bb] += w.z * h.z; acc[bb] += w.w * h.w;
                }
            }
        }
#pragma unroll
        for (int bb = 0; bb < 4; bb++) gtmp[(q << 7) + (j << 2) + bb] = acc[bb];
        __syncthreads();
        {
            float gi = gtmp[  0 + (j << 2) + q];
            float gf = gtmp[128 + (j << 2) + q];
            float gg = gtmp[256 + (j << 2) + q];
            float go = gtmp[384 + (j << 2) + q];
            float cn = sigf(gf) * c1 + sigf(gi) * tanhf_(gg);
            float hn = sigf(go) * tanhf_(cn);
            c1 = cn;
            pool += hn;
            uint32_t la = la1base + (uint32_t)(((1 - p) * 512 + (q << 7) + hlocal) * 4);
            st_dsmem(la, 0, hn); st_dsmem(la, 1, hn); st_dsmem(la, 2, hn); st_dsmem(la, 3, hn);
        }
        CLUSTER_SYNC();
        p ^= 1;
    }
    g_pooled[(size_t)(b0 + q) * Hh + hlocal] = pool * (1.0f / 2048.0f);
}

// ============================ kernel 4: out[b] = pooled[b,:] . lin_w + lin_b ============================
__global__ void final_kernel(const float* __restrict__ lw, const float* __restrict__ lb,
                             float* __restrict__ out) {
    int b = threadIdx.x;
    float acc = lb[0];
#pragma unroll 8
    for (int h = 0; h < Hh; h++) acc += g_pooled[b * Hh + h] * lw[h];
    out[b] = acc;
}

// ============================ launch ============================
extern "C" void kernel_launch(void* const* d_in, const int* in_sizes, int n_in,
                              void* d_out, int out_size) {
    (void)in_sizes; (void)n_in; (void)out_size;
    const float* x      = (const float*)d_in[0];
    const float* conv_w = (const float*)d_in[1];
    const float* conv_b = (const float*)d_in[2];
    const float* w_ih0  = (const float*)d_in[3];
    const float* w_hh0  = (const float*)d_in[4];
    const float* b_ih0  = (const float*)d_in[5];
    const float* b_hh0  = (const float*)d_in[6];
    const float* w_ih1  = (const float*)d_in[7];
    const float* w_hh1  = (const float*)d_in[8];
    const float* b_ih1  = (const float*)d_in[9];
    const float* b_hh1  = (const float*)d_in[10];
    const float* lin_w  = (const float*)d_in[11];
    const float* lin_b  = (const float*)d_in[12];
    float* out = (float*)d_out;

    cudaFuncSetAttribute(proj_kernel, cudaFuncAttributeMaxDynamicSharedMemorySize, PROJ_SMEM_BYTES);
    cudaFuncSetAttribute(lstm_kernel, cudaFuncAttributeMaxDynamicSharedMemorySize, LSTM_SMEM_BYTES);

    conv_kernel<<<dim3(Tt / 128, Bsz), 256>>>(x, conv_w, conv_b);
    proj_kernel<<<dim3((Bsz * Tt) / 128, Gg / 64), 256, PROJ_SMEM_BYTES>>>(w_ih0, b_ih0, b_hh0);
    lstm_kernel<<<128, 128, LSTM_SMEM_BYTES>>>(w_hh0, w_ih1, w_hh1, b_ih1, b_hh1);
    final_kernel<<<1, 128>>>(lin_w, lin_b, out);
}

// round 6
// speedup vs baseline: 1.3103x; 1.3103x over previous
#include <cuda_runtime.h>
#include <cstdint>
#include <cstddef>

#define Bsz 128
#define Tt  2048
#define Cin 16
#define CO  128
#define Hh  128
#define Gg  512

// -------- scratch (no allocations allowed; __device__ globals are the sanctioned path) ------
__device__ float g_seq[(size_t)Bsz * Tt * CO];      // conv output, [b*T+t][co]
__device__ float g_x0 [(size_t)Bsz * Tt * Gg];      // layer-0 input projection, [b*T+t][g]
__device__ float g_pooled[Bsz * Hh];                // mean over t of h1

// ---------------- packed f32x2 helpers ----------------
__device__ __forceinline__ unsigned long long fma2(unsigned long long a, unsigned long long b,
                                                   unsigned long long c) {
    unsigned long long d;
    asm("fma.rn.f32x2 %0, %1, %2, %3;" : "=l"(d) : "l"(a), "l"(b), "l"(c));
    return d;
}
__device__ __forceinline__ unsigned long long pack2(float lo, float hi) {
    unsigned long long r;
    asm("mov.b64 %0, {%1, %2};" : "=l"(r) : "f"(lo), "f"(hi));
    return r;
}
__device__ __forceinline__ void unpack2(unsigned long long v, float& a, float& b) {
    asm("mov.b64 {%0, %1}, %2;" : "=f"(a), "=f"(b) : "l"(v));
}
__device__ __forceinline__ float sum2(unsigned long long v) {
    float a, b; unpack2(v, a, b); return a + b;
}

// ============================ kernel 1: conv1d(k=3,pad=1) + LeakyReLU ============================
__global__ void conv_kernel(const float* __restrict__ x, const float* __restrict__ cw,
                            const float* __restrict__ cb) {
    __shared__ float xs[130 * 16];     // t0-1 .. t0+128
    __shared__ float wct[48 * 128];    // [(c*3+kk)][co]
    __shared__ float cbs[128];
    int tid = threadIdx.x;
    int b = blockIdx.y, t0 = blockIdx.x * 128;
    for (int i = tid; i < 130 * 16; i += 256) {
        int row = i >> 4, c = i & 15;
        int t = t0 - 1 + row;
        xs[i] = (t >= 0 && t < Tt) ? x[((size_t)b * Tt + t) * Cin + c] : 0.0f;
    }
    for (int i = tid; i < 48 * 128; i += 256) {
        int co = i / 48, rem = i % 48;          // rem = c*3 + kk
        wct[rem * 128 + co] = cw[i];
    }
    if (tid < 128) cbs[tid] = cb[tid];
    __syncthreads();
    for (int idx = tid; idx < 128 * 128; idx += 256) {
        int tl = idx >> 7, co = idx & 127;
        float acc = cbs[co];
#pragma unroll
        for (int c = 0; c < 16; c++)
#pragma unroll
            for (int kk = 0; kk < 3; kk++)
                acc += xs[(tl + kk) * 16 + c] * wct[(c * 3 + kk) * 128 + co];
        acc = acc >= 0.f ? acc : 0.01f * acc;
        g_seq[((size_t)b * Tt + t0 + tl) * CO + co] = acc;
    }
}

// ============================ kernel 2: x0 = seq @ w_ih0^T + (b_ih0+b_hh0) ============================
// block tile: 128 (M) x 64 (N), K = 128 fully in smem. 256 threads, 8x4 per thread, FFMA2 inner.
#define PROJ_SMEM_BYTES ((128 * 132 + 128 * 64) * 4)
__global__ void proj_kernel(const float* __restrict__ w, const float* __restrict__ bi,
                            const float* __restrict__ bh) {
    extern __shared__ float sm[];
    float* As = sm;                 // [128][132] (padded)
    float* Ws = sm + 128 * 132;     // [k=128][n=64]
    int tid = threadIdx.x;
    int mt = blockIdx.x, nt = blockIdx.y;
    const float* Ab = g_seq + (size_t)mt * 128 * CO;
    for (int i = tid; i < 128 * 32; i += 256) {
        int row = i >> 5, c4 = i & 31;
        float4 v = reinterpret_cast<const float4*>(Ab)[(size_t)row * 32 + c4];
        float* d = As + row * 132 + c4 * 4;
        d[0] = v.x; d[1] = v.y; d[2] = v.z; d[3] = v.w;
    }
    for (int i = tid; i < 64 * 128; i += 256) {
        int n = i >> 7, k = i & 127;
        Ws[k * 64 + n] = w[(size_t)(nt * 64 + n) * CO + k];
    }
    __syncthreads();
    int ty = tid >> 4, tx = tid & 15;
    unsigned long long acc2[8][2];
#pragma unroll
    for (int i = 0; i < 8; i++) { acc2[i][0] = 0ull; acc2[i][1] = 0ull; }
#pragma unroll 2
    for (int k0 = 0; k0 < 128; k0 += 4) {
        float4 av[8];
#pragma unroll
        for (int m = 0; m < 8; m++)
            av[m] = *reinterpret_cast<const float4*>(As + (ty * 8 + m) * 132 + k0);
#pragma unroll
        for (int kk = 0; kk < 4; kk++) {
            ulonglong2 w2 = *reinterpret_cast<const ulonglong2*>(Ws + (k0 + kk) * 64 + tx * 4);
#pragma unroll
            for (int m = 0; m < 8; m++) {
                float a = (kk == 0) ? av[m].x : (kk == 1) ? av[m].y : (kk == 2) ? av[m].z : av[m].w;
                unsigned long long a2 = pack2(a, a);
                acc2[m][0] = fma2(a2, w2.x, acc2[m][0]);
                acc2[m][1] = fma2(a2, w2.y, acc2[m][1]);
            }
        }
    }
    int n0 = nt * 64 + tx * 4;
    float bb0 = bi[n0] + bh[n0], bb1 = bi[n0 + 1] + bh[n0 + 1];
    float bb2 = bi[n0 + 2] + bh[n0 + 2], bb3 = bi[n0 + 3] + bh[n0 + 3];
#pragma unroll
    for (int i = 0; i < 8; i++) {
        float4 o;
        unpack2(acc2[i][0], o.x, o.y);
        unpack2(acc2[i][1], o.z, o.w);
        o.x += bb0; o.y += bb1; o.z += bb2; o.w += bb3;
        *reinterpret_cast<float4*>(g_x0 + ((size_t)mt * 128 + ty * 8 + i) * Gg + n0) = o;
    }
}

// ============================ kernel 3: persistent 2-layer LSTM, cluster-of-4 ============================
// 32 clusters x 4 CTAs, 256 threads/CTA. Cluster owns 4 batch rows.
// CTA r owns gate rows {g*128 + r*32 + j}. Threads split the k-dim in half (2 warps/SMSP).
// Software-pipelined: layer0(t+1) and layer1(t) between consecutive cluster syncs -> 1 sync/step.
// FFMA2 (fma.rn.f32x2) pairs over k; weights load natively as 64-bit pairs.

__device__ __forceinline__ float tanh_fast(float x) {
    float y; asm("tanh.approx.f32 %0, %1;" : "=f"(y) : "f"(x)); return y;
}
__device__ __forceinline__ float sig_fast(float x) {
    return fmaf(tanh_fast(0.5f * x), 0.5f, 0.5f);
}

#define LSTM_SMEM_BYTES ((3 * 128 * 132 + 2048 + 2048) * 4)

__device__ __forceinline__ void gemm_mat(const float* __restrict__ wrow,
                                         const float* __restrict__ hb,
                                         unsigned long long acc2[4]) {
    const ulonglong2* wp = reinterpret_cast<const ulonglong2*>(wrow);
#pragma unroll
    for (int kq = 0; kq < 16; kq++) {           // 4 k per iteration (2 f32x2 pairs)
        ulonglong2 wv = wp[kq];
#pragma unroll
        for (int bb = 0; bb < 4; bb++) {
            ulonglong2 hv = reinterpret_cast<const ulonglong2*>(hb + bb * 128)[kq];
            acc2[bb] = fma2(wv.x, hv.x, acc2[bb]);
            acc2[bb] = fma2(wv.y, hv.y, acc2[bb]);
        }
    }
}

__global__ void __cluster_dims__(4, 1, 1) __launch_bounds__(256, 1)
lstm_kernel(const float* __restrict__ whh0, const float* __restrict__ wih1,
            const float* __restrict__ whh1, const float* __restrict__ bih1,
            const float* __restrict__ bhh1) {
    extern __shared__ float sm[];
    float* w0   = sm;                       // W_hh0 slice [128 rows][132]
    float* w1   = w0 + 128 * 132;           // W_ih1 slice
    float* w2   = w1 + 128 * 132;           // W_hh1 slice
    float* hbuf = w2 + 128 * 132;           // [2 p][2 layer][4 bb][128 k]
    float* gtmp = hbuf + 2048;              // [2 layer][4 bb][2 half][128 row]

    int tid = threadIdx.x;
    int half = tid >> 7;                    // k-half for GEMM; also cell index for elementwise
    int wt = tid & 127, q = wt >> 5, j = wt & 31;
    uint32_t rank; asm("mov.u32 %0, %%cluster_ctarank;" : "=r"(rank));
    int r = (int)rank;
    int b0 = (blockIdx.x >> 2) * 4;
    int lr = q * 32 + j;                    // local weight row
    int rowg = (q << 7) + (r << 5) + j;     // global gate row

    // load weight slices
    for (int i = tid; i < 128 * 128; i += 256) {
        int rl = i >> 7, k = i & 127;
        int rg = ((rl >> 5) << 7) + (r << 5) + (rl & 31);
        w0[rl * 132 + k] = whh0[(size_t)rg * Hh + k];
        w1[rl * 132 + k] = wih1[(size_t)rg * Hh + k];
        w2[rl * 132 + k] = whh1[(size_t)rg * Hh + k];
    }
    for (int i = tid; i < 2048; i += 256) hbuf[i] = 0.f;

    float b1init = (half == 0) ? (bih1[rowg] + bhh1[rowg]) : 0.f;

    // elementwise role: (cell=half, batch=q, h index hl)
    int hl = (r << 5) + j;
    float cst = 0.f, pool = 0.f;

    float xn[4];
    if (half == 0) {
#pragma unroll
        for (int bb = 0; bb < 4; bb++)
            xn[bb] = g_x0[((size_t)(b0 + bb) * Tt) * Gg + rowg];
    }

    // precompute remote DSMEM base addresses for all 4 ranks
    uint32_t hb_la = (uint32_t)__cvta_generic_to_shared(hbuf);
    uint32_t rb[4];
#pragma unroll
    for (int rk = 0; rk < 4; rk++)
        asm("mapa.shared::cluster.u32 %0, %1, %2;" : "=r"(rb[rk]) : "r"(hb_la), "r"(rk));

    __syncthreads();
    asm volatile("barrier.cluster.arrive.aligned;" ::: "memory");
    asm volatile("barrier.cluster.wait.aligned;"   ::: "memory");

    const float* wr0 = w0 + lr * 132 + half * 64;
    const float* wr1 = w1 + lr * 132 + half * 64;
    const float* wr2 = w2 + lr * 132 + half * 64;

    int p = 0;
    for (int t = 0; t <= Tt; t++) {
        const float* hcur = hbuf + p * 1024 + half * 64;   // layer0 h base (+512 for layer1 h)
        // ---- GEMM A: gates0(t) = x0[t] + W_hh0 . h0   (skip on last iter)
        if (t < Tt) {
            unsigned long long acc2[4];
#pragma unroll
            for (int bb = 0; bb < 4; bb++) acc2[bb] = pack2(half == 0 ? xn[bb] : 0.f, 0.f);
            gemm_mat(wr0, hcur, acc2);
#pragma unroll
            for (int bb = 0; bb < 4; bb++)
                gtmp[((0 + bb) * 2 + half) * 128 + lr] = sum2(acc2[bb]);
        }
        // ---- GEMM B: gates1 = b1 + W_ih1 . h0 + W_hh1 . h1   (skip on first iter)
        if (t > 0) {
            unsigned long long acc2[4];
#pragma unroll
            for (int bb = 0; bb < 4; bb++) acc2[bb] = pack2(b1init, 0.f);
            gemm_mat(wr1, hcur, acc2);
            gemm_mat(wr2, hcur + 512, acc2);
#pragma unroll
            for (int bb = 0; bb < 4; bb++)
                gtmp[((4 + bb) * 2 + half) * 128 + lr] = sum2(acc2[bb]);
        }
        __syncthreads();
        // ---- elementwise: thread owns (cell=half, batch=q, h=hl)
        bool act = (half == 0) ? (t < Tt) : (t > 0);
        if (act) {
            int gb = (half * 4 + q) * 256;     // gtmp base for (layer, batch)
            float gv[4];
#pragma unroll
            for (int g = 0; g < 4; g++)
                gv[g] = gtmp[gb + (g << 5) + j] + gtmp[gb + 128 + (g << 5) + j];
            float cn = sig_fast(gv[1]) * cst + sig_fast(gv[0]) * tanh_fast(gv[2]);
            float hn = sig_fast(gv[3]) * tanh_fast(cn);
            cst = cn;
            if (half) pool += hn;
            uint32_t off = (uint32_t)((((p ^ 1) << 10) + (half << 9) + (q << 7) + hl) << 2);
#pragma unroll
            for (int rk = 0; rk < 4; rk++)
                asm volatile("st.shared::cluster.f32 [%0], %1;"
                             :: "r"(rb[rk] + off), "f"(hn) : "memory");
        }
        asm volatile("barrier.cluster.arrive.aligned;" ::: "memory");
        if (half == 0 && t + 1 < Tt) {
#pragma unroll
            for (int bb = 0; bb < 4; bb++)
                xn[bb] = g_x0[((size_t)(b0 + bb) * Tt + (t + 1)) * Gg + rowg];
        }
        asm volatile("barrier.cluster.wait.aligned;" ::: "memory");
        p ^= 1;
    }
    if (half == 1)
        g_pooled[(size_t)(b0 + q) * Hh + hl] = pool * (1.0f / 2048.0f);
}

// ============================ kernel 4: out[b] = pooled[b,:] . lin_w + lin_b ============================
__global__ void final_kernel(const float* __restrict__ lw, const float* __restrict__ lb,
                             float* __restrict__ out) {
    int b = threadIdx.x;
    float acc = lb[0];
#pragma unroll 8
    for (int h = 0; h < Hh; h++) acc += g_pooled[b * Hh + h] * lw[h];
    out[b] = acc;
}

// ============================ launch ============================
extern "C" void kernel_launch(void* const* d_in, const int* in_sizes, int n_in,
                              void* d_out, int out_size) {
    (void)in_sizes; (void)n_in; (void)out_size;
    const float* x      = (const float*)d_in[0];
    const float* conv_w = (const float*)d_in[1];
    const float* conv_b = (const float*)d_in[2];
    const float* w_ih0  = (const float*)d_in[3];
    const float* w_hh0  = (const float*)d_in[4];
    const float* b_ih0  = (const float*)d_in[5];
    const float* b_hh0  = (const float*)d_in[6];
    const float* w_ih1  = (const float*)d_in[7];
    const float* w_hh1  = (const float*)d_in[8];
    const float* b_ih1  = (const float*)d_in[9];
    const float* b_hh1  = (const float*)d_in[10];
    const float* lin_w  = (const float*)d_in[11];
    const float* lin_b  = (const float*)d_in[12];
    float* out = (float*)d_out;

    cudaFuncSetAttribute(proj_kernel, cudaFuncAttributeMaxDynamicSharedMemorySize, PROJ_SMEM_BYTES);
    cudaFuncSetAttribute(lstm_kernel, cudaFuncAttributeMaxDynamicSharedMemorySize, LSTM_SMEM_BYTES);

    conv_kernel<<<dim3(Tt / 128, Bsz), 256>>>(x, conv_w, conv_b);
    proj_kernel<<<dim3((Bsz * Tt) / 128, Gg / 64), 256, PROJ_SMEM_BYTES>>>(w_ih0, b_ih0, b_hh0);
    lstm_kernel<<<128, 256, LSTM_SMEM_BYTES>>>(w_hh0, w_ih1, w_hh1, b_ih1, b_hh1);
    final_kernel<<<1, 128>>>(lin_w, lin_b, out);
}